// round 13
// baseline (speedup 1.0000x reference)
#include <cuda_runtime.h>
#include <cuda_fp16.h>
#include <math.h>
#include <stdint.h>

// ---------------- problem constants ----------------
#define BATCH 512
#define T_IN 64
#define IN_DIM 16
#define HS 32
#define OUT_DIM 32
#define H 960
#define G3 2880
#define T_PRED 48

#define KC 160              // K-chunk (divides 960)
#define NCH 6               // h-pass chunks
#define MTILE 128
#define NTILE 96            // 3 gates x 32 units
#define NTHR 256

// smem: [bias 1024B][3 stages]; fp16 rows: 160 elems (320B) + 16B pad = 336B
#define ROWB 336
#define ABYTES (MTILE * ROWB)      // 43008
#define BBYTES (NTILE * ROWB)      // 32256
#define STAGE (ABYTES + BBYTES)    // 75264
#define SMEM_BYTES (1024 + 3 * STAGE)   // 226816
// epilogue planes (alias stage ring after final sync)
#define MSTRIDE 100
#define N2STRIDE 36
#define N2OFF 51200

// ---------------- device scratch ----------------
#define WBIG (G3 * NCH * KC)
#define WSM  (G3 * KC)
#define HSN  (NCH * BATCH * KC)

__device__ __half g_W[6][WBIG];      // eWhh0,eWih1,eWhh1,dWhh0,dWih1,dWhh1
__device__ __half g_Wsm[2][WSM];     // eWih0, dWih0 (K padded to KC)
__device__ float  g_h0f[2][BATCH * H];
__device__ float  g_h1f[2][BATCH * H];
__device__ __half g_h0a[2][HSN];
__device__ __half g_h1a[2][HSN];
__device__ __half g_xin[T_IN * BATCH * KC];
__device__ __half g_ll[BATCH * KC];
__device__ __half g_xd[BATCH * KC];
__device__ float  g_linWt[H * OUT_DIM];       // transposed linW
__device__ int    g_lflag[T_PRED][4];

// ---------------- helpers ----------------
__device__ __forceinline__ uint32_t smem_u32(const void* p) {
    uint32_t a;
    asm("{ .reg .u64 t; cvta.to.shared.u64 t, %1; cvt.u32.u64 %0, t; }" : "=r"(a) : "l"(p));
    return a;
}
__device__ __forceinline__ void cp16(uint32_t dst, const void* src) {
    asm volatile("cp.async.cg.shared.global [%0], [%1], 16;" :: "r"(dst), "l"(src) : "memory");
}
#define CP_COMMIT() asm volatile("cp.async.commit_group;" ::: "memory")
#define CP_WAIT(n)  asm volatile("cp.async.wait_group %0;" :: "n"(n) : "memory")

__device__ __forceinline__ void ldm4(uint32_t (&r)[4], uint32_t a) {
    asm volatile("ldmatrix.sync.aligned.m8n8.x4.shared.b16 {%0,%1,%2,%3}, [%4];"
        : "=r"(r[0]), "=r"(r[1]), "=r"(r[2]), "=r"(r[3]) : "r"(a));
}
__device__ __forceinline__ void mma_f16(float (&d)[4], const uint32_t (&a)[4],
                                        uint32_t b0, uint32_t b1) {
    asm volatile(
        "mma.sync.aligned.m16n8k16.row.col.f32.f16.f16.f32 "
        "{%0,%1,%2,%3}, {%4,%5,%6,%7}, {%8,%9}, {%0,%1,%2,%3};"
        : "+f"(d[0]), "+f"(d[1]), "+f"(d[2]), "+f"(d[3])
        : "r"(a[0]), "r"(a[1]), "r"(a[2]), "r"(a[3]), "r"(b0), "r"(b1));
}
__device__ __forceinline__ float sigf(float v) { return 1.0f / (1.0f + expf(-v)); }

// ---------------- fused GRU step; h-chunks first, x-chunk last ----------------
// If linflag != null: CTAs with ub<6 first compute out/xd rows for their m-block
// (inline linear head), arrive on linflag[mb]; all CTAs check flag before x-chunk.
__global__ __launch_bounds__(NTHR, 1)
void gru_step_h(const __half* __restrict__ xA, int ncx,
                const __half* __restrict__ hA,
                const __half* __restrict__ w1, const __half* __restrict__ w2,
                const float* __restrict__ bih, const float* __restrict__ bhh,
                const float* __restrict__ hprevf, float* __restrict__ houtf,
                __half* __restrict__ hAout,
                float* __restrict__ hcat, int hcat_ld,
                int* __restrict__ linflag,
                const float* __restrict__ linh, const float* __restrict__ linWt,
                const float* __restrict__ linb,
                float* __restrict__ outp, int out_ld, __half* __restrict__ xdout)
{
    extern __shared__ char smem[];
    float* sbias = (float*)smem;
    const uint32_t sb = smem_u32(smem);

    const int tid  = threadIdx.x;
    const int lane = tid & 31;
    const int w    = tid >> 5;
    const int wm   = w & 3;
    const int wn   = w >> 2;
    const int mb   = blockIdx.x;
    const int m0   = mb * MTILE;
    const int ub   = blockIdx.y;
    const int nc   = NCH + ncx;

    if (tid < 192) {
        int g = (tid < 96) ? (tid >> 5) : ((tid - 96) >> 5);
        int j = tid & 31;
        sbias[tid] = (tid < 96) ? bih[g * H + ub * 32 + j] : bhh[g * H + ub * 32 + j];
    }

    float acc[2][6][4];
    float accn[2][4][4];
#pragma unroll
    for (int m2 = 0; m2 < 2; ++m2) {
#pragma unroll
        for (int f = 0; f < 6; ++f)
#pragma unroll
            for (int i = 0; i < 4; ++i) acc[m2][f][i] = 0.f;
#pragma unroll
        for (int f = 0; f < 4; ++f)
#pragma unroll
            for (int i = 0; i < 4; ++i) accn[m2][f][i] = 0.f;
    }

    const int lrow = (lane & 7) + ((lane >> 3) & 1) * 8;
    const int lcol = (lane >> 4) * 16;
    const uint32_t aoff = (uint32_t)(wm * 32 + lrow) * ROWB + lcol;
    const uint32_t boff = ABYTES + (uint32_t)(wn * 48 + lrow) * ROWB + lcol;

    auto issue_load = [&](int c) {
        if (linflag && c >= NCH) {   // x-chunk consumes this launch's linear output
            while (*((volatile int*)&linflag[mb]) < 6) { }
        }
        const __half* ap = (c < NCH) ? (hA + ((size_t)c * BATCH + m0) * KC)
                                     : (xA + ((size_t)(c - NCH) * BATCH + m0) * KC);
        const __half* bp = (c < NCH) ? (w2 + ((size_t)c * G3 + ub * NTILE) * KC)
                                     : (w1 + ((size_t)(c - NCH) * G3 + ub * NTILE) * KC);
        const char* asrc = (const char*)ap;
        const char* bsrc = (const char*)bp;
        uint32_t d = sb + 1024 + (uint32_t)(c % 3) * STAGE;
#pragma unroll
        for (int i = 0; i < 10; ++i) {             // A: 2560 x 16B
            int u = tid + i * NTHR;
            cp16(d + (u / 20) * ROWB + (u % 20) * 16, asrc + (size_t)u * 16);
        }
#pragma unroll
        for (int i = 0; i < 8; ++i) {              // B: 1920 x 16B
            int u = tid + i * NTHR;
            if (u < 1920)
                cp16(d + ABYTES + (u / 20) * ROWB + (u % 20) * 16, bsrc + (size_t)u * 16);
        }
        CP_COMMIT();
    };

    issue_load(0); issue_load(1);

    // inline linear head (producer CTAs, before mainloop; loads overlap)
    if (linflag != nullptr && ub < 6) {
        const int lr0 = ub * 22;
        const int lr1 = (lr0 + 22 < 128) ? lr0 + 22 : 128;
        for (int lr = lr0 + (tid >> 5); lr < lr1; lr += 8) {
            const int b = m0 + lr;
            const float* hrow = linh + (size_t)b * H;
            float s = 0.f;
#pragma unroll 8
            for (int k = 0; k < H; ++k)
                s = fmaf(hrow[k], linWt[k * OUT_DIM + lane], s);
            s += linb[lane];
            outp[(size_t)b * out_ld + lane] = s;
            xdout[(size_t)b * KC + lane] = __float2half_rn(s);
        }
        __syncthreads();
        __threadfence();
        if (tid == 0) atomicAdd(&linflag[mb], 1);
    }

#define CHUNK_BODY(SPLIT)                                                       \
    {                                                                           \
        _Pragma("unroll")                                                       \
        for (int kk = 0; kk < 10; ++kk) {                                       \
            uint32_t a0[4], a1[4], b0[4], b1[4], b2[4];                         \
            ldm4(a0, stage + aoff + kk * 32);                                   \
            ldm4(a1, stage + aoff + 16 * ROWB + kk * 32);                       \
            ldm4(b0, stage + boff + kk * 32);                                   \
            ldm4(b1, stage + boff + 16 * ROWB + kk * 32);                       \
            ldm4(b2, stage + boff + 32 * ROWB + kk * 32);                       \
            mma_f16(acc[0][0], a0, b0[0], b0[2]);                               \
            mma_f16(acc[1][0], a1, b0[0], b0[2]);                               \
            mma_f16(acc[0][1], a0, b0[1], b0[3]);                               \
            mma_f16(acc[1][1], a1, b0[1], b0[3]);                               \
            if (SPLIT) {                                                        \
                mma_f16(accn[0][0], a0, b1[0], b1[2]);                          \
                mma_f16(accn[1][0], a1, b1[0], b1[2]);                          \
                mma_f16(accn[0][1], a0, b1[1], b1[3]);                          \
                mma_f16(accn[1][1], a1, b1[1], b1[3]);                          \
                mma_f16(accn[0][2], a0, b2[0], b2[2]);                          \
                mma_f16(accn[1][2], a1, b2[0], b2[2]);                          \
                mma_f16(accn[0][3], a0, b2[1], b2[3]);                          \
                mma_f16(accn[1][3], a1, b2[1], b2[3]);                          \
            } else {                                                            \
                mma_f16(acc[0][2], a0, b1[0], b1[2]);                           \
                mma_f16(acc[1][2], a1, b1[0], b1[2]);                           \
                mma_f16(acc[0][3], a0, b1[1], b1[3]);                           \
                mma_f16(acc[1][3], a1, b1[1], b1[3]);                           \
                mma_f16(acc[0][4], a0, b2[0], b2[2]);                           \
                mma_f16(acc[1][4], a1, b2[0], b2[2]);                           \
                mma_f16(acc[0][5], a0, b2[1], b2[3]);                           \
                mma_f16(acc[1][5], a1, b2[1], b2[3]);                           \
            }                                                                   \
        }                                                                       \
    }

    // 3-stage single-sync: wait(<=1) -> barrier -> prefetch (c+2) -> consume c
    for (int c = 0; c < nc; ++c) {
        if (c + 1 < nc) { CP_WAIT(1); } else { CP_WAIT(0); }
        __syncthreads();
        if (c + 2 < nc) issue_load(c + 2);
        const uint32_t stage = sb + 1024 + (uint32_t)(c % 3) * STAGE;
        if (c < NCH && wn == 1) CHUNK_BODY(1) else CHUNK_BODY(0)
    }
#undef CHUNK_BODY
    __syncthreads();

    // ---------------- epilogue ----------------
    float* Mp = (float*)(smem + 1024);
    float* Np = (float*)(smem + 1024 + N2OFF);
    {
        const int rb = wm * 32 + (lane >> 2);
        const int cb = wn * 48 + (lane & 3) * 2;
#pragma unroll
        for (int m2 = 0; m2 < 2; ++m2) {
#pragma unroll
            for (int f = 0; f < 6; ++f) {
                int r = rb + m2 * 16;
                int cc = cb + f * 8;
                *(float2*)&Mp[r * MSTRIDE + cc]       = make_float2(acc[m2][f][0], acc[m2][f][1]);
                *(float2*)&Mp[(r + 8) * MSTRIDE + cc] = make_float2(acc[m2][f][2], acc[m2][f][3]);
            }
        }
        if (wn == 1) {
            const int cb2 = (lane & 3) * 2;
#pragma unroll
            for (int m2 = 0; m2 < 2; ++m2) {
#pragma unroll
                for (int f = 0; f < 4; ++f) {
                    int r = rb + m2 * 16;
                    int cc = cb2 + f * 8;
                    *(float2*)&Np[r * N2STRIDE + cc]       = make_float2(accn[m2][f][0], accn[m2][f][1]);
                    *(float2*)&Np[(r + 8) * N2STRIDE + cc] = make_float2(accn[m2][f][2], accn[m2][f][3]);
                }
            }
        }
    }
    __syncthreads();

    {
        const int row = tid >> 1;
        const int j0  = (tid & 1) * 16;
        const int brow = m0 + row;
        const int cj = ub / 5;
        const int kb = (ub % 5) * 32;

        float hv[16];
#pragma unroll
        for (int v = 0; v < 8; ++v) {
            int j = j0 + v * 2;
            float2 R  = *(float2*)&Mp[row * MSTRIDE + j];
            float2 Z  = *(float2*)&Mp[row * MSTRIDE + 32 + j];
            float2 NX = *(float2*)&Mp[row * MSTRIDE + 64 + j];
            float2 NH = *(float2*)&Np[row * N2STRIDE + j];
            float2 HP = *(const float2*)(hprevf + (size_t)brow * H + ub * 32 + j);
#pragma unroll
            for (int e = 0; e < 2; ++e) {
                int jj = j + e;
                float rr = sigf(((e ? R.y : R.x))  + sbias[jj]      + sbias[96 + jj]);
                float zz = sigf(((e ? Z.y : Z.x))  + sbias[32 + jj] + sbias[128 + jj]);
                float nn = tanhf(((e ? NX.y : NX.x)) + sbias[64 + jj]
                                 + rr * (((e ? NH.y : NH.x)) + sbias[160 + jj]));
                hv[j - j0 + e] = (1.0f - zz) * nn + zz * (e ? HP.y : HP.x);
            }
        }
        const size_t ob = (size_t)brow * H + ub * 32 + j0;
#pragma unroll
        for (int q = 0; q < 4; ++q)
            *(float4*)(houtf + ob + q * 4) = make_float4(hv[q*4], hv[q*4+1], hv[q*4+2], hv[q*4+3]);
        if (hcat) {
            const size_t cbo = (size_t)brow * hcat_ld + ub * 32 + j0;
#pragma unroll
            for (int q = 0; q < 4; ++q)
                *(float4*)(hcat + cbo + q * 4) = make_float4(hv[q*4], hv[q*4+1], hv[q*4+2], hv[q*4+3]);
        }
        __half hh[16];
#pragma unroll
        for (int i = 0; i < 16; ++i) hh[i] = __float2half_rn(hv[i]);
        const size_t so = ((size_t)cj * BATCH + brow) * KC + kb + j0;
        *(uint4*)(hAout + so)     = ((uint4*)hh)[0];
        *(uint4*)(hAout + so + 8) = ((uint4*)hh)[1];
    }
}

// ---------------- trailing linear (last decoder output only) ----------------
__global__ __launch_bounds__(256)
void linear_kernel(const float* __restrict__ h,
                   const float* __restrict__ W, const float* __restrict__ bias,
                   float* __restrict__ out, int out_ld)
{
    __shared__ float Ws[64][33];
    __shared__ float hs[8][64];
    const int tid = threadIdx.x;
    const int o = tid & 31;
    const int bl = tid >> 5;
    const int b0 = blockIdx.x * 8;

    float acc = 0.f;
    for (int k0 = 0; k0 < H; k0 += 64) {
#pragma unroll
        for (int i = 0; i < 8; ++i) {
            int idx = tid + i * 256;
            Ws[idx & 63][idx >> 6] = W[(size_t)(idx >> 6) * H + k0 + (idx & 63)];
        }
#pragma unroll
        for (int i = 0; i < 2; ++i) {
            int idx = tid + i * 256;
            hs[idx >> 6][idx & 63] = h[(size_t)(b0 + (idx >> 6)) * H + k0 + (idx & 63)];
        }
        __syncthreads();
#pragma unroll
        for (int kk = 0; kk < 64; ++kk)
            acc = fmaf(hs[bl][kk], Ws[kk][o], acc);
        __syncthreads();
    }
    out[(size_t)(b0 + bl) * out_ld + o] = acc + bias[o];
}

// ---------------- prep (consolidated) ----------------
struct WPrep { const float* src[8]; };

__global__ void prep_weights(WPrep wp, __half* __restrict__ Wb, __half* __restrict__ Wsm)
{
    const int y = blockIdx.y;
    if (y < 6) {
        const float* W = wp.src[y];
        __half* dst = Wb + (size_t)y * WBIG;
        int total = G3 * NCH * KC;
        for (int idx = blockIdx.x * blockDim.x + threadIdx.x; idx < total; idx += gridDim.x * blockDim.x) {
            int k = idx % KC;
            int q = idx / KC;
            int n = q % G3;
            int c = q / G3;
            int ubl = n / 96, rem = n % 96, g = rem >> 5, jj = rem & 31;
            int row = g * H + ubl * 32 + jj;
            dst[idx] = __float2half_rn(W[(size_t)row * H + c * KC + k]);
        }
    } else {
        const float* W = wp.src[y];
        const int K = (y == 6) ? IN_DIM : HS;
        __half* dst = Wsm + (size_t)(y - 6) * WSM;
        int total = G3 * KC;
        for (int idx = blockIdx.x * blockDim.x + threadIdx.x; idx < total; idx += gridDim.x * blockDim.x) {
            int k = idx % KC;
            int n = idx / KC;
            int ubl = n / 96, rem = n % 96, g = rem >> 5, jj = rem & 31;
            int row = g * H + ubl * 32 + jj;
            float v = (k < K) ? W[(size_t)row * K + k] : 0.f;
            dst[idx] = __float2half_rn(v);
        }
    }
}

__global__ void prep_acts(const float* __restrict__ in_data, const float* __restrict__ ll_src,
                          const float* __restrict__ linW,
                          __half* __restrict__ xin, __half* __restrict__ xll,
                          float* __restrict__ linWt)
{
    const int t1 = T_IN * BATCH * KC;
    const int t2 = t1 + BATCH * KC;
    const int t3 = t2 + H * OUT_DIM;
    for (int idx = blockIdx.x * blockDim.x + threadIdx.x; idx < t3; idx += gridDim.x * blockDim.x) {
        if (idx < t1) {
            int k = idx % KC;
            int q = idx / KC;
            int b = q & (BATCH - 1);
            int t = q >> 9;
            float v = (k < IN_DIM) ? in_data[((size_t)b * T_IN + t) * IN_DIM + k] : 0.f;
            xin[idx] = __float2half_rn(v);
        } else if (idx < t2) {
            int i = idx - t1;
            int k = i % KC;
            int b = i / KC;
            float v = (k < HS) ? ll_src[(size_t)b * HS + k] : 0.f;
            xll[i] = __float2half_rn(v);
        } else {
            int i = idx - t2;
            int o = i % OUT_DIM;
            int k = i / OUT_DIM;
            linWt[i] = linW[(size_t)o * H + k];
        }
    }
}

__global__ void clear_a(float* __restrict__ h0f0, float* __restrict__ h1f0)
{
    const int n = BATCH * H;
    for (int i = blockIdx.x * blockDim.x + threadIdx.x; i < 2 * n; i += gridDim.x * blockDim.x) {
        if (i < n) h0f0[i] = 0.f; else h1f0[i - n] = 0.f;
    }
}

__global__ void clear_b(__half* __restrict__ h0a0, __half* __restrict__ h1a0,
                        __half* __restrict__ xd, int* __restrict__ lflag)
{
    const int n = HSN;
    const int t2 = 2 * n + BATCH * KC;
    const int t3 = t2 + T_PRED * 4;
    for (int i = blockIdx.x * blockDim.x + threadIdx.x; i < t3; i += gridDim.x * blockDim.x) {
        if (i < n) h0a0[i] = __half(0.f);
        else if (i < 2 * n) h1a0[i - n] = __half(0.f);
        else if (i < t2) xd[i - 2 * n] = __half(0.f);
        else lflag[i - t2] = 0;
    }
}

// ---------------- host ----------------
extern "C" void kernel_launch(void* const* d_in, const int* in_sizes, int n_in,
                              void* d_out, int out_size)
{
    const float* in_data  = (const float*)d_in[0];
    const float* last_loc = (const float*)d_in[1];
    const float* eWih0 = (const float*)d_in[3];
    const float* eWhh0 = (const float*)d_in[4];
    const float* ebih0 = (const float*)d_in[5];
    const float* ebhh0 = (const float*)d_in[6];
    const float* eWih1 = (const float*)d_in[7];
    const float* eWhh1 = (const float*)d_in[8];
    const float* ebih1 = (const float*)d_in[9];
    const float* ebhh1 = (const float*)d_in[10];
    const float* dWih0 = (const float*)d_in[11];
    const float* dWhh0 = (const float*)d_in[12];
    const float* dbih0 = (const float*)d_in[13];
    const float* dbhh0 = (const float*)d_in[14];
    const float* dWih1 = (const float*)d_in[15];
    const float* dWhh1 = (const float*)d_in[16];
    const float* dbih1 = (const float*)d_in[17];
    const float* dbhh1 = (const float*)d_in[18];
    const float* linW  = (const float*)d_in[19];
    const float* linb  = (const float*)d_in[20];

    float* outputs = (float*)d_out;
    float* hidden  = (float*)d_out + (size_t)BATCH * T_PRED * OUT_DIM;

    __half (*Wb)[WBIG];         cudaGetSymbolAddress((void**)&Wb, g_W);
    __half (*Wsm)[WSM];         cudaGetSymbolAddress((void**)&Wsm, g_Wsm);
    float (*h0f)[BATCH * H];    cudaGetSymbolAddress((void**)&h0f, g_h0f);
    float (*h1f)[BATCH * H];    cudaGetSymbolAddress((void**)&h1f, g_h1f);
    __half (*h0a)[HSN];         cudaGetSymbolAddress((void**)&h0a, g_h0a);
    __half (*h1a)[HSN];         cudaGetSymbolAddress((void**)&h1a, g_h1a);
    __half* xin = nullptr;      cudaGetSymbolAddress((void**)&xin, g_xin);
    __half* xll = nullptr;      cudaGetSymbolAddress((void**)&xll, g_ll);
    __half* xd  = nullptr;      cudaGetSymbolAddress((void**)&xd, g_xd);
    float*  lwt = nullptr;      cudaGetSymbolAddress((void**)&lwt, g_linWt);
    int (*lflag)[4];            cudaGetSymbolAddress((void**)&lflag, g_lflag);

    cudaFuncSetAttribute(gru_step_h, cudaFuncAttributeMaxDynamicSharedMemorySize, SMEM_BYTES);

    WPrep wp;
    wp.src[0] = eWhh0; wp.src[1] = eWih1; wp.src[2] = eWhh1;
    wp.src[3] = dWhh0; wp.src[4] = dWih1; wp.src[5] = dWhh1;
    wp.src[6] = eWih0; wp.src[7] = dWih0;
    prep_weights<<<dim3(512, 8), 256>>>(wp, Wb[0], Wsm[0]);                 // launch 0
    prep_acts<<<1024, 256>>>(in_data, last_loc, linW, xin, xll, lwt);       // launch 1
    clear_a<<<512, 256>>>(h0f[0], h1f[0]);                                  // launch 2
    clear_b<<<512, 256>>>(h0a[0], h1a[0], xd, &lflag[0][0]);                // launch 3

    dim3 grid(BATCH / MTILE, H / 32);   // (4, 30)
    int p0 = 0, p1 = 0;
    const int out_ld = T_PRED * OUT_DIM;
    const int hid_ld = T_PRED * 2 * H;

    // ---- encoder ----
    for (int t = 0; t < T_IN; ++t) {
        gru_step_h<<<grid, NTHR, SMEM_BYTES>>>(
            xin + (size_t)t * BATCH * KC, 1,
            h0a[p0], Wsm[0], Wb[0],
            ebih0, ebhh0, h0f[p0], h0f[1 - p0], h0a[1 - p0],
            nullptr, 0,
            nullptr, nullptr, nullptr, nullptr, nullptr, 0, nullptr);
        p0 ^= 1;
        gru_step_h<<<grid, NTHR, SMEM_BYTES>>>(
            h0a[p0], NCH,
            h1a[p1], Wb[1], Wb[2],
            ebih1, ebhh1, h1f[p1], h1f[1 - p1], h1a[1 - p1],
            nullptr, 0,
            nullptr, nullptr, nullptr, nullptr, nullptr, 0, nullptr);
        p1 ^= 1;
    }

    // ---- decoder: L0 carries the previous step's linear head inline ----
    for (int t = 0; t < T_PRED; ++t) {
        const __half* xAp = (t == 0) ? xll : xd;
        int* fl = (t == 0) ? nullptr : &lflag[t][0];
        gru_step_h<<<grid, NTHR, SMEM_BYTES>>>(
            xAp, 1,
            h0a[p0], Wsm[1], Wb[3],
            dbih0, dbhh0, h0f[p0], h0f[1 - p0], h0a[1 - p0],
            hidden + (size_t)t * 2 * H, hid_ld,
            fl, h1f[p1], lwt, linb,
            outputs + (size_t)(t - 1) * OUT_DIM, out_ld, xd);
        p0 ^= 1;
        gru_step_h<<<grid, NTHR, SMEM_BYTES>>>(
            h0a[p0], NCH,
            h1a[p1], Wb[4], Wb[5],
            dbih1, dbhh1, h1f[p1], h1f[1 - p1], h1a[1 - p1],
            hidden + (size_t)t * 2 * H + H, hid_ld,
            nullptr, nullptr, nullptr, nullptr, nullptr, 0, nullptr);
        p1 ^= 1;
    }

    // final output (t = T_PRED-1) linear
    linear_kernel<<<BATCH / 8, 256>>>(h1f[p1], linW, linb,
                                      outputs + (size_t)(T_PRED - 1) * OUT_DIM, out_ld);
}

// round 14
// speedup vs baseline: 1.4734x; 1.4734x over previous
#include <cuda_runtime.h>
#include <cuda_fp16.h>
#include <math.h>
#include <stdint.h>

// ---------------- problem constants ----------------
#define BATCH 512
#define T_IN 64
#define IN_DIM 16
#define HS 32
#define OUT_DIM 32
#define H 960
#define G3 2880
#define T_PRED 48

#define KC 160              // K-chunk (divides 960)
#define NCH 6               // h-pass chunks
#define MTILE 64
#define NTILE 96            // 3 gates x 32 units
#define NTHR 128

// smem: [bias 1024B][2 stages]; fp16 rows: 160 elems (320B) + 16B pad = 336B
#define ROWB 336
#define ABYTES (MTILE * ROWB)      // 21504
#define BBYTES (NTILE * ROWB)      // 32256
#define STAGE (ABYTES + BBYTES)    // 53760
#define SMEM_BYTES (1024 + 2 * STAGE)   // 108544  -> 2 CTAs/SM
// epilogue planes (alias stage ring after final sync)
#define MSTRIDE 100
#define N2STRIDE 36
#define N2OFF 25600

// ---------------- device scratch ----------------
#define WBIG (G3 * NCH * KC)
#define WSM  (G3 * KC)
#define HSN  (NCH * BATCH * KC)

__device__ __half g_W[6][WBIG];      // eWhh0,eWih1,eWhh1,dWhh0,dWih1,dWhh1
__device__ __half g_Wsm[2][WSM];     // eWih0, dWih0 (K padded to KC)
__device__ float  g_h0f[2][BATCH * H];
__device__ float  g_h1f[2][BATCH * H];
__device__ __half g_h0a[2][HSN];
__device__ __half g_h1a[2][HSN];
__device__ __half g_xin[T_IN * BATCH * KC];
__device__ __half g_ll[BATCH * KC];
__device__ __half g_xd[BATCH * KC];

// ---------------- helpers ----------------
__device__ __forceinline__ uint32_t smem_u32(const void* p) {
    uint32_t a;
    asm("{ .reg .u64 t; cvta.to.shared.u64 t, %1; cvt.u32.u64 %0, t; }" : "=r"(a) : "l"(p));
    return a;
}
__device__ __forceinline__ void cp16(uint32_t dst, const void* src) {
    asm volatile("cp.async.cg.shared.global [%0], [%1], 16;" :: "r"(dst), "l"(src) : "memory");
}
#define CP_COMMIT() asm volatile("cp.async.commit_group;" ::: "memory")
#define CP_WAIT0()  asm volatile("cp.async.wait_group 0;" ::: "memory")

__device__ __forceinline__ void ldm4(uint32_t (&r)[4], uint32_t a) {
    asm volatile("ldmatrix.sync.aligned.m8n8.x4.shared.b16 {%0,%1,%2,%3}, [%4];"
        : "=r"(r[0]), "=r"(r[1]), "=r"(r[2]), "=r"(r[3]) : "r"(a));
}
__device__ __forceinline__ void mma_f16(float (&d)[4], const uint32_t (&a)[4],
                                        uint32_t b0, uint32_t b1) {
    asm volatile(
        "mma.sync.aligned.m16n8k16.row.col.f32.f16.f16.f32 "
        "{%0,%1,%2,%3}, {%4,%5,%6,%7}, {%8,%9}, {%0,%1,%2,%3};"
        : "+f"(d[0]), "+f"(d[1]), "+f"(d[2]), "+f"(d[3])
        : "r"(a[0]), "r"(a[1]), "r"(a[2]), "r"(a[3]), "r"(b0), "r"(b1));
}
__device__ __forceinline__ float sigf(float v) { return 1.0f / (1.0f + expf(-v)); }

// ---------------- fused GRU step (fp16 mma, M=64 tile, 2 CTAs/SM) ----------------
__global__ __launch_bounds__(NTHR, 2)
void gru_step_h(const __half* __restrict__ xA, int ncx,
                const __half* __restrict__ hA,
                const __half* __restrict__ w1, const __half* __restrict__ w2,
                const float* __restrict__ bih, const float* __restrict__ bhh,
                const float* __restrict__ hprevf, float* __restrict__ houtf,
                __half* __restrict__ hAout,
                float* __restrict__ hcat, int hcat_ld)
{
    extern __shared__ char smem[];
    float* sbias = (float*)smem;
    const uint32_t sb = smem_u32(smem);

    const int tid  = threadIdx.x;
    const int lane = tid & 31;
    const int w    = tid >> 5;   // 0..3
    const int wm   = w & 1;      // m-block (32 rows)
    const int wn   = w >> 1;     // n-half (48 cols)
    const int m0   = blockIdx.x * MTILE;
    const int ub   = blockIdx.y;
    const int nc   = ncx + NCH;

    for (int i = tid; i < 192; i += NTHR) {
        int g = (i < 96) ? (i >> 5) : ((i - 96) >> 5);
        int j = i & 31;
        sbias[i] = (i < 96) ? bih[g * H + ub * 32 + j] : bhh[g * H + ub * 32 + j];
    }

    // acc = r/z (both passes) + n-gate x-pass; accn = n-gate h-pass (wn==1 only)
    float acc[2][6][4];
    float accn[2][4][4];
#pragma unroll
    for (int m2 = 0; m2 < 2; ++m2) {
#pragma unroll
        for (int f = 0; f < 6; ++f)
#pragma unroll
            for (int i = 0; i < 4; ++i) acc[m2][f][i] = 0.f;
#pragma unroll
        for (int f = 0; f < 4; ++f)
#pragma unroll
            for (int i = 0; i < 4; ++i) accn[m2][f][i] = 0.f;
    }

    const int lrow = (lane & 7) + ((lane >> 3) & 1) * 8;
    const int lcol = (lane >> 4) * 16;
    const uint32_t aoff = (uint32_t)(wm * 32 + lrow) * ROWB + lcol;
    const uint32_t boff = ABYTES + (uint32_t)(wn * 48 + lrow) * ROWB + lcol;

    auto issue_load = [&](int c) {
        const __half* ap = (c < ncx) ? (xA + ((size_t)c * BATCH + m0) * KC)
                                     : (hA + ((size_t)(c - ncx) * BATCH + m0) * KC);
        const __half* bp = (c < ncx) ? (w1 + ((size_t)c * G3 + ub * NTILE) * KC)
                                     : (w2 + ((size_t)(c - ncx) * G3 + ub * NTILE) * KC);
        const char* asrc = (const char*)ap;
        const char* bsrc = (const char*)bp;
        uint32_t d = sb + 1024 + (uint32_t)(c & 1) * STAGE;
        // A: 64 rows x 320B = 1280 x 16B
#pragma unroll
        for (int i = 0; i < 10; ++i) {
            int u = tid + i * NTHR;
            cp16(d + (u / 20) * ROWB + (u % 20) * 16, asrc + (size_t)u * 16);
        }
        // B: 96 rows x 320B = 1920 x 16B
#pragma unroll
        for (int i = 0; i < 15; ++i) {
            int u = tid + i * NTHR;
            cp16(d + ABYTES + (u / 20) * ROWB + (u % 20) * 16, bsrc + (size_t)u * 16);
        }
        CP_COMMIT();
    };

    issue_load(0);

#define CHUNK_BODY(SPLIT)                                                       \
    {                                                                           \
        _Pragma("unroll")                                                       \
        for (int kk = 0; kk < 10; ++kk) {                                       \
            uint32_t a0[4], a1[4], b0[4], b1[4], b2[4];                         \
            ldm4(a0, stage + aoff + kk * 32);                                   \
            ldm4(a1, stage + aoff + 16 * ROWB + kk * 32);                       \
            ldm4(b0, stage + boff + kk * 32);                                   \
            ldm4(b1, stage + boff + 16 * ROWB + kk * 32);                       \
            ldm4(b2, stage + boff + 32 * ROWB + kk * 32);                       \
            mma_f16(acc[0][0], a0, b0[0], b0[2]);                               \
            mma_f16(acc[1][0], a1, b0[0], b0[2]);                               \
            mma_f16(acc[0][1], a0, b0[1], b0[3]);                               \
            mma_f16(acc[1][1], a1, b0[1], b0[3]);                               \
            if (SPLIT) {                                                        \
                mma_f16(accn[0][0], a0, b1[0], b1[2]);                          \
                mma_f16(accn[1][0], a1, b1[0], b1[2]);                          \
                mma_f16(accn[0][1], a0, b1[1], b1[3]);                          \
                mma_f16(accn[1][1], a1, b1[1], b1[3]);                          \
                mma_f16(accn[0][2], a0, b2[0], b2[2]);                          \
                mma_f16(accn[1][2], a1, b2[0], b2[2]);                          \
                mma_f16(accn[0][3], a0, b2[1], b2[3]);                          \
                mma_f16(accn[1][3], a1, b2[1], b2[3]);                          \
            } else {                                                            \
                mma_f16(acc[0][2], a0, b1[0], b1[2]);                           \
                mma_f16(acc[1][2], a1, b1[0], b1[2]);                           \
                mma_f16(acc[0][3], a0, b1[1], b1[3]);                           \
                mma_f16(acc[1][3], a1, b1[1], b1[3]);                           \
                mma_f16(acc[0][4], a0, b2[0], b2[2]);                           \
                mma_f16(acc[1][4], a1, b2[0], b2[2]);                           \
                mma_f16(acc[0][5], a0, b2[1], b2[3]);                           \
                mma_f16(acc[1][5], a1, b2[1], b2[3]);                           \
            }                                                                   \
        }                                                                       \
    }

    // 2-stage double buffer: wait(0) -> barrier -> issue(c+1) -> consume(c)
    for (int c = 0; c < nc; ++c) {
        CP_WAIT0();
        __syncthreads();
        if (c + 1 < nc) issue_load(c + 1);
        const uint32_t stage = sb + 1024 + (uint32_t)(c & 1) * STAGE;
        if (c >= ncx && wn == 1) CHUNK_BODY(1) else CHUNK_BODY(0)
    }
#undef CHUNK_BODY
    __syncthreads();   // ring fully consumed before plane overwrite

    // ---------------- epilogue: accums -> smem planes -> gate math ----------------
    float* Mp = (float*)(smem + 1024);
    float* Np = (float*)(smem + 1024 + N2OFF);
    {
        const int rb = wm * 32 + (lane >> 2);
        const int cb = wn * 48 + (lane & 3) * 2;
#pragma unroll
        for (int m2 = 0; m2 < 2; ++m2) {
#pragma unroll
            for (int f = 0; f < 6; ++f) {
                int r = rb + m2 * 16;
                int cc = cb + f * 8;
                *(float2*)&Mp[r * MSTRIDE + cc]       = make_float2(acc[m2][f][0], acc[m2][f][1]);
                *(float2*)&Mp[(r + 8) * MSTRIDE + cc] = make_float2(acc[m2][f][2], acc[m2][f][3]);
            }
        }
        if (wn == 1) {
            const int cb2 = (lane & 3) * 2;
#pragma unroll
            for (int m2 = 0; m2 < 2; ++m2) {
#pragma unroll
                for (int f = 0; f < 4; ++f) {
                    int r = rb + m2 * 16;
                    int cc = cb2 + f * 8;
                    *(float2*)&Np[r * N2STRIDE + cc]       = make_float2(accn[m2][f][0], accn[m2][f][1]);
                    *(float2*)&Np[(r + 8) * N2STRIDE + cc] = make_float2(accn[m2][f][2], accn[m2][f][3]);
                }
            }
        }
    }
    __syncthreads();

    {
        const int row = tid >> 1;            // 0..63
        const int j0  = (tid & 1) * 16;
        const int brow = m0 + row;
        const int cj = ub / 5;
        const int kb = (ub % 5) * 32;

        float hv[16];
#pragma unroll
        for (int v = 0; v < 8; ++v) {
            int j = j0 + v * 2;
            float2 R  = *(float2*)&Mp[row * MSTRIDE + j];
            float2 Z  = *(float2*)&Mp[row * MSTRIDE + 32 + j];
            float2 NX = *(float2*)&Mp[row * MSTRIDE + 64 + j];
            float2 NH = *(float2*)&Np[row * N2STRIDE + j];
            float2 HP = *(const float2*)(hprevf + (size_t)brow * H + ub * 32 + j);
#pragma unroll
            for (int e = 0; e < 2; ++e) {
                int jj = j + e;
                float rr = sigf(((e ? R.y : R.x))  + sbias[jj]      + sbias[96 + jj]);
                float zz = sigf(((e ? Z.y : Z.x))  + sbias[32 + jj] + sbias[128 + jj]);
                float nn = tanhf(((e ? NX.y : NX.x)) + sbias[64 + jj]
                                 + rr * (((e ? NH.y : NH.x)) + sbias[160 + jj]));
                hv[j - j0 + e] = (1.0f - zz) * nn + zz * (e ? HP.y : HP.x);
            }
        }
        const size_t ob = (size_t)brow * H + ub * 32 + j0;
#pragma unroll
        for (int q = 0; q < 4; ++q)
            *(float4*)(houtf + ob + q * 4) = make_float4(hv[q*4], hv[q*4+1], hv[q*4+2], hv[q*4+3]);
        if (hcat) {
            const size_t cbo = (size_t)brow * hcat_ld + ub * 32 + j0;
#pragma unroll
            for (int q = 0; q < 4; ++q)
                *(float4*)(hcat + cbo + q * 4) = make_float4(hv[q*4], hv[q*4+1], hv[q*4+2], hv[q*4+3]);
        }
        __half hh[16];
#pragma unroll
        for (int i = 0; i < 16; ++i) hh[i] = __float2half_rn(hv[i]);
        const size_t so = ((size_t)cj * BATCH + brow) * KC + kb + j0;
        *(uint4*)(hAout + so)     = ((uint4*)hh)[0];
        *(uint4*)(hAout + so + 8) = ((uint4*)hh)[1];
    }
}

// ---------------- linear head ----------------
__global__ __launch_bounds__(256)
void linear_kernel(const float* __restrict__ h,
                   const float* __restrict__ W, const float* __restrict__ bias,
                   float* __restrict__ out, int out_ld,
                   __half* __restrict__ xdA)
{
    __shared__ float Ws[64][33];
    __shared__ float hs[8][64];
    const int tid = threadIdx.x;
    const int o = tid & 31;
    const int bl = tid >> 5;
    const int b0 = blockIdx.x * 8;

    float acc = 0.f;
    for (int k0 = 0; k0 < H; k0 += 64) {
#pragma unroll
        for (int i = 0; i < 8; ++i) {
            int idx = tid + i * 256;
            Ws[idx & 63][idx >> 6] = W[(size_t)(idx >> 6) * H + k0 + (idx & 63)];
        }
#pragma unroll
        for (int i = 0; i < 2; ++i) {
            int idx = tid + i * 256;
            hs[idx >> 6][idx & 63] = h[(size_t)(b0 + (idx >> 6)) * H + k0 + (idx & 63)];
        }
        __syncthreads();
#pragma unroll
        for (int kk = 0; kk < 64; ++kk)
            acc = fmaf(hs[bl][kk], Ws[kk][o], acc);
        __syncthreads();
    }
    float v = acc + bias[o];
    int b = b0 + bl;
    out[(size_t)b * out_ld + o] = v;
    xdA[(size_t)b * KC + o] = __float2half_rn(v);
}

// ---------------- prep (consolidated) ----------------
struct WPrep { const float* src[8]; };

__global__ void prep_weights(WPrep wp, __half* __restrict__ Wb, __half* __restrict__ Wsm)
{
    const int y = blockIdx.y;
    if (y < 6) {
        const float* W = wp.src[y];
        __half* dst = Wb + (size_t)y * WBIG;
        int total = G3 * NCH * KC;
        for (int idx = blockIdx.x * blockDim.x + threadIdx.x; idx < total; idx += gridDim.x * blockDim.x) {
            int k = idx % KC;
            int q = idx / KC;
            int n = q % G3;
            int c = q / G3;
            int ubl = n / 96, rem = n % 96, g = rem >> 5, jj = rem & 31;
            int row = g * H + ubl * 32 + jj;
            dst[idx] = __float2half_rn(W[(size_t)row * H + c * KC + k]);
        }
    } else {
        const float* W = wp.src[y];
        const int K = (y == 6) ? IN_DIM : HS;
        __half* dst = Wsm + (size_t)(y - 6) * WSM;
        int total = G3 * KC;
        for (int idx = blockIdx.x * blockDim.x + threadIdx.x; idx < total; idx += gridDim.x * blockDim.x) {
            int k = idx % KC;
            int n = idx / KC;
            int ubl = n / 96, rem = n % 96, g = rem >> 5, jj = rem & 31;
            int row = g * H + ubl * 32 + jj;
            float v = (k < K) ? W[(size_t)row * K + k] : 0.f;
            dst[idx] = __float2half_rn(v);
        }
    }
}

__global__ void prep_acts(const float* __restrict__ in_data, const float* __restrict__ ll_src,
                          __half* __restrict__ xin, __half* __restrict__ xll)
{
    const int t1 = T_IN * BATCH * KC;
    const int t2 = t1 + BATCH * KC;
    for (int idx = blockIdx.x * blockDim.x + threadIdx.x; idx < t2; idx += gridDim.x * blockDim.x) {
        if (idx < t1) {
            int k = idx % KC;
            int q = idx / KC;
            int b = q & (BATCH - 1);
            int t = q >> 9;
            float v = (k < IN_DIM) ? in_data[((size_t)b * T_IN + t) * IN_DIM + k] : 0.f;
            xin[idx] = __float2half_rn(v);
        } else {
            int i = idx - t1;
            int k = i % KC;
            int b = i / KC;
            float v = (k < HS) ? ll_src[(size_t)b * HS + k] : 0.f;
            xll[i] = __float2half_rn(v);
        }
    }
}

__global__ void clear_a(float* __restrict__ h0f0, float* __restrict__ h1f0)
{
    const int n = BATCH * H;
    for (int i = blockIdx.x * blockDim.x + threadIdx.x; i < 2 * n; i += gridDim.x * blockDim.x) {
        if (i < n) h0f0[i] = 0.f; else h1f0[i - n] = 0.f;
    }
}

__global__ void clear_b(__half* __restrict__ h0a0, __half* __restrict__ h1a0,
                        __half* __restrict__ xd)
{
    const int n = HSN;
    const int t2 = 2 * n + BATCH * KC;
    for (int i = blockIdx.x * blockDim.x + threadIdx.x; i < t2; i += gridDim.x * blockDim.x) {
        if (i < n) h0a0[i] = __half(0.f);
        else if (i < 2 * n) h1a0[i - n] = __half(0.f);
        else xd[i - 2 * n] = __half(0.f);
    }
}

// ---------------- host ----------------
extern "C" void kernel_launch(void* const* d_in, const int* in_sizes, int n_in,
                              void* d_out, int out_size)
{
    const float* in_data  = (const float*)d_in[0];
    const float* last_loc = (const float*)d_in[1];
    const float* eWih0 = (const float*)d_in[3];
    const float* eWhh0 = (const float*)d_in[4];
    const float* ebih0 = (const float*)d_in[5];
    const float* ebhh0 = (const float*)d_in[6];
    const float* eWih1 = (const float*)d_in[7];
    const float* eWhh1 = (const float*)d_in[8];
    const float* ebih1 = (const float*)d_in[9];
    const float* ebhh1 = (const float*)d_in[10];
    const float* dWih0 = (const float*)d_in[11];
    const float* dWhh0 = (const float*)d_in[12];
    const float* dbih0 = (const float*)d_in[13];
    const float* dbhh0 = (const float*)d_in[14];
    const float* dWih1 = (const float*)d_in[15];
    const float* dWhh1 = (const float*)d_in[16];
    const float* dbih1 = (const float*)d_in[17];
    const float* dbhh1 = (const float*)d_in[18];
    const float* linW  = (const float*)d_in[19];
    const float* linb  = (const float*)d_in[20];

    float* outputs = (float*)d_out;
    float* hidden  = (float*)d_out + (size_t)BATCH * T_PRED * OUT_DIM;

    __half (*Wb)[WBIG];         cudaGetSymbolAddress((void**)&Wb, g_W);
    __half (*Wsm)[WSM];         cudaGetSymbolAddress((void**)&Wsm, g_Wsm);
    float (*h0f)[BATCH * H];    cudaGetSymbolAddress((void**)&h0f, g_h0f);
    float (*h1f)[BATCH * H];    cudaGetSymbolAddress((void**)&h1f, g_h1f);
    __half (*h0a)[HSN];         cudaGetSymbolAddress((void**)&h0a, g_h0a);
    __half (*h1a)[HSN];         cudaGetSymbolAddress((void**)&h1a, g_h1a);
    __half* xin = nullptr;      cudaGetSymbolAddress((void**)&xin, g_xin);
    __half* xll = nullptr;      cudaGetSymbolAddress((void**)&xll, g_ll);
    __half* xd  = nullptr;      cudaGetSymbolAddress((void**)&xd, g_xd);

    cudaFuncSetAttribute(gru_step_h, cudaFuncAttributeMaxDynamicSharedMemorySize, SMEM_BYTES);

    WPrep wp;
    wp.src[0] = eWhh0; wp.src[1] = eWih1; wp.src[2] = eWhh1;
    wp.src[3] = dWhh0; wp.src[4] = dWih1; wp.src[5] = dWhh1;
    wp.src[6] = eWih0; wp.src[7] = dWih0;
    prep_weights<<<dim3(512, 8), 256>>>(wp, Wb[0], Wsm[0]);
    prep_acts<<<1024, 256>>>(in_data, last_loc, xin, xll);
    clear_a<<<512, 256>>>(h0f[0], h1f[0]);
    clear_b<<<512, 256>>>(h0a[0], h1a[0], xd);

    dim3 grid(BATCH / MTILE, H / 32);   // (8, 30) = 240 CTAs, 2/SM
    int p0 = 0, p1 = 0;
    const int out_ld = T_PRED * OUT_DIM;
    const int hid_ld = T_PRED * 2 * H;

    // ---- encoder ----
    for (int t = 0; t < T_IN; ++t) {
        gru_step_h<<<grid, NTHR, SMEM_BYTES>>>(
            xin + (size_t)t * BATCH * KC, 1,
            h0a[p0], Wsm[0], Wb[0],
            ebih0, ebhh0, h0f[p0], h0f[1 - p0], h0a[1 - p0],
            nullptr, 0);
        p0 ^= 1;
        gru_step_h<<<grid, NTHR, SMEM_BYTES>>>(
            h0a[p0], NCH,
            h1a[p1], Wb[1], Wb[2],
            ebih1, ebhh1, h1f[p1], h1f[1 - p1], h1a[1 - p1],
            nullptr, 0);
        p1 ^= 1;
    }

    // ---- decoder ----
    for (int t = 0; t < T_PRED; ++t) {
        const __half* xAp = (t == 0) ? xll : xd;
        gru_step_h<<<grid, NTHR, SMEM_BYTES>>>(
            xAp, 1,
            h0a[p0], Wsm[1], Wb[3],
            dbih0, dbhh0, h0f[p0], h0f[1 - p0], h0a[1 - p0],
            hidden + (size_t)t * 2 * H, hid_ld);
        p0 ^= 1;
        gru_step_h<<<grid, NTHR, SMEM_BYTES>>>(
            h0a[p0], NCH,
            h1a[p1], Wb[4], Wb[5],
            dbih1, dbhh1, h1f[p1], h1f[1 - p1], h1a[1 - p1],
            hidden + (size_t)t * 2 * H + H, hid_ld);
        p1 ^= 1;
        linear_kernel<<<BATCH / 8, 256>>>(h1f[p1], linW, linb,
                                          outputs + (size_t)t * OUT_DIM, out_ld, xd);
    }
}

// round 15
// speedup vs baseline: 1.5754x; 1.0692x over previous
#include <cuda_runtime.h>
#include <cuda_fp16.h>
#include <math.h>
#include <stdint.h>

// ---------------- problem constants ----------------
#define BATCH 512
#define T_IN 64
#define IN_DIM 16
#define HS 32
#define OUT_DIM 32
#define H 960
#define G3 2880
#define T_PRED 48

#define KC 160              // K-chunk (divides 960)
#define NCH 6               // h-pass chunks
#define MTILE 128
#define NTILE 96            // 3 gates x 32 units
#define NTHR 256

// smem: [bias 1024B][2 stages]; fp16 rows: 160 elems (320B) + 16B pad = 336B
#define ROWB 336
#define ABYTES (MTILE * ROWB)      // 43008
#define BBYTES (NTILE * ROWB)      // 32256
#define STAGE (ABYTES + BBYTES)    // 75264
#define SMEM_BYTES (1024 + 2 * STAGE)   // 151552
// epilogue planes (alias stage ring after final sync)
#define MSTRIDE 100
#define N2STRIDE 36
#define N2OFF 51200

// ---------------- device scratch ----------------
#define WBIG (G3 * NCH * KC)
#define WSM  (G3 * KC)
#define HSN  (NCH * BATCH * KC)

__device__ __half g_W[6][WBIG];      // eWhh0,eWih1,eWhh1,dWhh0,dWih1,dWhh1
__device__ __half g_Wsm[2][WSM];     // eWih0, dWih0 (K padded to KC)
__device__ float  g_h0f[2][BATCH * H];
__device__ float  g_h1f[2][BATCH * H];
__device__ __half g_h0a[2][HSN];
__device__ __half g_h1a[2][HSN];
__device__ __half g_xin[T_IN * BATCH * KC];
__device__ __half g_ll[BATCH * KC];
__device__ __half g_xd[BATCH * KC];

// ---------------- helpers ----------------
__device__ __forceinline__ uint32_t smem_u32(const void* p) {
    uint32_t a;
    asm("{ .reg .u64 t; cvta.to.shared.u64 t, %1; cvt.u32.u64 %0, t; }" : "=r"(a) : "l"(p));
    return a;
}
__device__ __forceinline__ void cp16(uint32_t dst, const void* src) {
    asm volatile("cp.async.cg.shared.global [%0], [%1], 16;" :: "r"(dst), "l"(src) : "memory");
}
#define CP_COMMIT() asm volatile("cp.async.commit_group;" ::: "memory")
#define CP_WAIT0()  asm volatile("cp.async.wait_group 0;" ::: "memory")

__device__ __forceinline__ void ldm4(uint32_t (&r)[4], uint32_t a) {
    asm volatile("ldmatrix.sync.aligned.m8n8.x4.shared.b16 {%0,%1,%2,%3}, [%4];"
        : "=r"(r[0]), "=r"(r[1]), "=r"(r[2]), "=r"(r[3]) : "r"(a));
}
__device__ __forceinline__ void mma_f16(float (&d)[4], const uint32_t (&a)[4],
                                        uint32_t b0, uint32_t b1) {
    asm volatile(
        "mma.sync.aligned.m16n8k16.row.col.f32.f16.f16.f32 "
        "{%0,%1,%2,%3}, {%4,%5,%6,%7}, {%8,%9}, {%0,%1,%2,%3};"
        : "+f"(d[0]), "+f"(d[1]), "+f"(d[2]), "+f"(d[3])
        : "r"(a[0]), "r"(a[1]), "r"(a[2]), "r"(a[3]), "r"(b0), "r"(b1));
}
// fast transcendentals (args are O(10); far from overflow)
__device__ __forceinline__ float sigf(float v) {
    return __fdividef(1.0f, 1.0f + __expf(-v));
}
__device__ __forceinline__ float tanhfast(float x) {
    float t = __expf(2.0f * x);
    return 1.0f - __fdividef(2.0f, t + 1.0f);
}

// ---------------- fused GRU step (fp16 mma, K=160 chunks, 2-stage) ----------------
// xkk: kk-iterations for x-chunks (2 when x-K<=32, 10 when full)
__global__ __launch_bounds__(NTHR, 1)
void gru_step_h(const __half* __restrict__ xA, int ncx, int xkk,
                const __half* __restrict__ hA,
                const __half* __restrict__ w1, const __half* __restrict__ w2,
                const float* __restrict__ bih, const float* __restrict__ bhh,
                const float* __restrict__ hprevf, float* __restrict__ houtf,
                __half* __restrict__ hAout,
                float* __restrict__ hcat, int hcat_ld)
{
    extern __shared__ char smem[];
    float* sbias = (float*)smem;
    const uint32_t sb = smem_u32(smem);

    const int tid  = threadIdx.x;
    const int lane = tid & 31;
    const int w    = tid >> 5;
    const int wm   = w & 3;      // m-block (32 rows)
    const int wn   = w >> 2;     // n-half (48 cols)
    const int m0   = blockIdx.x * MTILE;
    const int ub   = blockIdx.y;
    const int nc   = ncx + NCH;

    if (tid < 192) {
        int g = (tid < 96) ? (tid >> 5) : ((tid - 96) >> 5);
        int j = tid & 31;
        sbias[tid] = (tid < 96) ? bih[g * H + ub * 32 + j] : bhh[g * H + ub * 32 + j];
    }

    // acc = r/z (both passes) + n-gate x-pass; accn = n-gate h-pass (wn==1 only)
    float acc[2][6][4];
    float accn[2][4][4];
#pragma unroll
    for (int m2 = 0; m2 < 2; ++m2) {
#pragma unroll
        for (int f = 0; f < 6; ++f)
#pragma unroll
            for (int i = 0; i < 4; ++i) acc[m2][f][i] = 0.f;
#pragma unroll
        for (int f = 0; f < 4; ++f)
#pragma unroll
            for (int i = 0; i < 4; ++i) accn[m2][f][i] = 0.f;
    }

    const int lrow = (lane & 7) + ((lane >> 3) & 1) * 8;
    const int lcol = (lane >> 4) * 16;
    const uint32_t aoff = (uint32_t)(wm * 32 + lrow) * ROWB + lcol;
    const uint32_t boff = ABYTES + (uint32_t)(wn * 48 + lrow) * ROWB + lcol;

    auto issue_load = [&](int c) {
        const __half* ap = (c < ncx) ? (xA + ((size_t)c * BATCH + m0) * KC)
                                     : (hA + ((size_t)(c - ncx) * BATCH + m0) * KC);
        const __half* bp = (c < ncx) ? (w1 + ((size_t)c * G3 + ub * NTILE) * KC)
                                     : (w2 + ((size_t)(c - ncx) * G3 + ub * NTILE) * KC);
        const char* asrc = (const char*)ap;
        const char* bsrc = (const char*)bp;
        uint32_t d = sb + 1024 + (uint32_t)(c & 1) * STAGE;
#pragma unroll
        for (int i = 0; i < 10; ++i) {             // A: 2560 x 16B
            int u = tid + i * NTHR;
            cp16(d + (u / 20) * ROWB + (u % 20) * 16, asrc + (size_t)u * 16);
        }
#pragma unroll
        for (int i = 0; i < 8; ++i) {              // B: 1920 x 16B
            int u = tid + i * NTHR;
            if (u < 1920)
                cp16(d + ABYTES + (u / 20) * ROWB + (u % 20) * 16, bsrc + (size_t)u * 16);
        }
        CP_COMMIT();
    };

    issue_load(0);

#define CHUNK_BODY(SPLIT, KKN)                                                  \
    {                                                                           \
        _Pragma("unroll")                                                       \
        for (int kk = 0; kk < KKN; ++kk) {                                      \
            uint32_t a0[4], a1[4], b0[4], b1[4], b2[4];                         \
            ldm4(a0, stage + aoff + kk * 32);                                   \
            ldm4(a1, stage + aoff + 16 * ROWB + kk * 32);                       \
            ldm4(b0, stage + boff + kk * 32);                                   \
            ldm4(b1, stage + boff + 16 * ROWB + kk * 32);                       \
            ldm4(b2, stage + boff + 32 * ROWB + kk * 32);                       \
            mma_f16(acc[0][0], a0, b0[0], b0[2]);                               \
            mma_f16(acc[1][0], a1, b0[0], b0[2]);                               \
            mma_f16(acc[0][1], a0, b0[1], b0[3]);                               \
            mma_f16(acc[1][1], a1, b0[1], b0[3]);                               \
            if (SPLIT) {                                                        \
                mma_f16(accn[0][0], a0, b1[0], b1[2]);                          \
                mma_f16(accn[1][0], a1, b1[0], b1[2]);                          \
                mma_f16(accn[0][1], a0, b1[1], b1[3]);                          \
                mma_f16(accn[1][1], a1, b1[1], b1[3]);                          \
                mma_f16(accn[0][2], a0, b2[0], b2[2]);                          \
                mma_f16(accn[1][2], a1, b2[0], b2[2]);                          \
                mma_f16(accn[0][3], a0, b2[1], b2[3]);                          \
                mma_f16(accn[1][3], a1, b2[1], b2[3]);                          \
            } else {                                                            \
                mma_f16(acc[0][2], a0, b1[0], b1[2]);                           \
                mma_f16(acc[1][2], a1, b1[0], b1[2]);                           \
                mma_f16(acc[0][3], a0, b1[1], b1[3]);                           \
                mma_f16(acc[1][3], a1, b1[1], b1[3]);                           \
                mma_f16(acc[0][4], a0, b2[0], b2[2]);                           \
                mma_f16(acc[1][4], a1, b2[0], b2[2]);                           \
                mma_f16(acc[0][5], a0, b2[1], b2[3]);                           \
                mma_f16(acc[1][5], a1, b2[1], b2[3]);                           \
            }                                                                   \
        }                                                                       \
    }

    // 2-stage double buffer: wait(0) -> barrier -> issue(c+1) -> consume(c)
    for (int c = 0; c < nc; ++c) {
        CP_WAIT0();
        __syncthreads();
        if (c + 1 < nc) issue_load(c + 1);
        const uint32_t stage = sb + 1024 + (uint32_t)(c & 1) * STAGE;
        if (c < ncx) {
            if (xkk == 2) CHUNK_BODY(0, 2) else CHUNK_BODY(0, 10)
        } else if (wn == 1) {
            CHUNK_BODY(1, 10)
        } else {
            CHUNK_BODY(0, 10)
        }
    }
#undef CHUNK_BODY
    __syncthreads();   // ring fully consumed before plane overwrite

    // ---------------- epilogue: accums -> smem planes -> gate math ----------------
    float* Mp = (float*)(smem + 1024);
    float* Np = (float*)(smem + 1024 + N2OFF);
    {
        const int rb = wm * 32 + (lane >> 2);
        const int cb = wn * 48 + (lane & 3) * 2;
#pragma unroll
        for (int m2 = 0; m2 < 2; ++m2) {
#pragma unroll
            for (int f = 0; f < 6; ++f) {
                int r = rb + m2 * 16;
                int cc = cb + f * 8;
                *(float2*)&Mp[r * MSTRIDE + cc]       = make_float2(acc[m2][f][0], acc[m2][f][1]);
                *(float2*)&Mp[(r + 8) * MSTRIDE + cc] = make_float2(acc[m2][f][2], acc[m2][f][3]);
            }
        }
        if (wn == 1) {
            const int cb2 = (lane & 3) * 2;
#pragma unroll
            for (int m2 = 0; m2 < 2; ++m2) {
#pragma unroll
                for (int f = 0; f < 4; ++f) {
                    int r = rb + m2 * 16;
                    int cc = cb2 + f * 8;
                    *(float2*)&Np[r * N2STRIDE + cc]       = make_float2(accn[m2][f][0], accn[m2][f][1]);
                    *(float2*)&Np[(r + 8) * N2STRIDE + cc] = make_float2(accn[m2][f][2], accn[m2][f][3]);
                }
            }
        }
    }
    __syncthreads();

    {
        const int row = tid >> 1;
        const int j0  = (tid & 1) * 16;
        const int brow = m0 + row;
        const int cj = ub / 5;
        const int kb = (ub % 5) * 32;

        float hv[16];
#pragma unroll
        for (int v = 0; v < 8; ++v) {
            int j = j0 + v * 2;
            float2 R  = *(float2*)&Mp[row * MSTRIDE + j];
            float2 Z  = *(float2*)&Mp[row * MSTRIDE + 32 + j];
            float2 NX = *(float2*)&Mp[row * MSTRIDE + 64 + j];
            float2 NH = *(float2*)&Np[row * N2STRIDE + j];
            float2 HP = *(const float2*)(hprevf + (size_t)brow * H + ub * 32 + j);
#pragma unroll
            for (int e = 0; e < 2; ++e) {
                int jj = j + e;
                float rr = sigf(((e ? R.y : R.x))  + sbias[jj]      + sbias[96 + jj]);
                float zz = sigf(((e ? Z.y : Z.x))  + sbias[32 + jj] + sbias[128 + jj]);
                float nn = tanhfast(((e ? NX.y : NX.x)) + sbias[64 + jj]
                                    + rr * (((e ? NH.y : NH.x)) + sbias[160 + jj]));
                hv[j - j0 + e] = (1.0f - zz) * nn + zz * (e ? HP.y : HP.x);
            }
        }
        const size_t ob = (size_t)brow * H + ub * 32 + j0;
#pragma unroll
        for (int q = 0; q < 4; ++q)
            *(float4*)(houtf + ob + q * 4) = make_float4(hv[q*4], hv[q*4+1], hv[q*4+2], hv[q*4+3]);
        if (hcat) {
            const size_t cbo = (size_t)brow * hcat_ld + ub * 32 + j0;
#pragma unroll
            for (int q = 0; q < 4; ++q)
                *(float4*)(hcat + cbo + q * 4) = make_float4(hv[q*4], hv[q*4+1], hv[q*4+2], hv[q*4+3]);
        }
        __half hh[16];
#pragma unroll
        for (int i = 0; i < 16; ++i) hh[i] = __float2half_rn(hv[i]);
        const size_t so = ((size_t)cj * BATCH + brow) * KC + kb + j0;
        *(uint4*)(hAout + so)     = ((uint4*)hh)[0];
        *(uint4*)(hAout + so + 8) = ((uint4*)hh)[1];
    }
}

// ---------------- linear head ----------------
__global__ __launch_bounds__(256)
void linear_kernel(const float* __restrict__ h,
                   const float* __restrict__ W, const float* __restrict__ bias,
                   float* __restrict__ out, int out_ld,
                   __half* __restrict__ xdA)
{
    __shared__ float Ws[64][33];
    __shared__ float hs[8][64];
    const int tid = threadIdx.x;
    const int o = tid & 31;
    const int bl = tid >> 5;
    const int b0 = blockIdx.x * 8;

    float acc = 0.f;
    for (int k0 = 0; k0 < H; k0 += 64) {
#pragma unroll
        for (int i = 0; i < 8; ++i) {
            int idx = tid + i * 256;
            Ws[idx & 63][idx >> 6] = W[(size_t)(idx >> 6) * H + k0 + (idx & 63)];
        }
#pragma unroll
        for (int i = 0; i < 2; ++i) {
            int idx = tid + i * 256;
            hs[idx >> 6][idx & 63] = h[(size_t)(b0 + (idx >> 6)) * H + k0 + (idx & 63)];
        }
        __syncthreads();
#pragma unroll
        for (int kk = 0; kk < 64; ++kk)
            acc = fmaf(hs[bl][kk], Ws[kk][o], acc);
        __syncthreads();
    }
    float v = acc + bias[o];
    int b = b0 + bl;
    out[(size_t)b * out_ld + o] = v;
    xdA[(size_t)b * KC + o] = __float2half_rn(v);
}

// ---------------- prep (consolidated) ----------------
struct WPrep { const float* src[8]; };

__global__ void prep_weights(WPrep wp, __half* __restrict__ Wb, __half* __restrict__ Wsm)
{
    const int y = blockIdx.y;
    if (y < 6) {
        const float* W = wp.src[y];
        __half* dst = Wb + (size_t)y * WBIG;
        int total = G3 * NCH * KC;
        for (int idx = blockIdx.x * blockDim.x + threadIdx.x; idx < total; idx += gridDim.x * blockDim.x) {
            int k = idx % KC;
            int q = idx / KC;
            int n = q % G3;
            int c = q / G3;
            int ubl = n / 96, rem = n % 96, g = rem >> 5, jj = rem & 31;
            int row = g * H + ubl * 32 + jj;
            dst[idx] = __float2half_rn(W[(size_t)row * H + c * KC + k]);
        }
    } else {
        const float* W = wp.src[y];
        const int K = (y == 6) ? IN_DIM : HS;
        __half* dst = Wsm + (size_t)(y - 6) * WSM;
        int total = G3 * KC;
        for (int idx = blockIdx.x * blockDim.x + threadIdx.x; idx < total; idx += gridDim.x * blockDim.x) {
            int k = idx % KC;
            int n = idx / KC;
            int ubl = n / 96, rem = n % 96, g = rem >> 5, jj = rem & 31;
            int row = g * H + ubl * 32 + jj;
            float v = (k < K) ? W[(size_t)row * K + k] : 0.f;
            dst[idx] = __float2half_rn(v);
        }
    }
}

__global__ void prep_acts(const float* __restrict__ in_data, const float* __restrict__ ll_src,
                          __half* __restrict__ xin, __half* __restrict__ xll)
{
    const int t1 = T_IN * BATCH * KC;
    const int t2 = t1 + BATCH * KC;
    for (int idx = blockIdx.x * blockDim.x + threadIdx.x; idx < t2; idx += gridDim.x * blockDim.x) {
        if (idx < t1) {
            int k = idx % KC;
            int q = idx / KC;
            int b = q & (BATCH - 1);
            int t = q >> 9;
            float v = (k < IN_DIM) ? in_data[((size_t)b * T_IN + t) * IN_DIM + k] : 0.f;
            xin[idx] = __float2half_rn(v);
        } else {
            int i = idx - t1;
            int k = i % KC;
            int b = i / KC;
            float v = (k < HS) ? ll_src[(size_t)b * HS + k] : 0.f;
            xll[i] = __float2half_rn(v);
        }
    }
}

__global__ void clear_a(float* __restrict__ h0f0, float* __restrict__ h1f0)
{
    const int n = BATCH * H;
    for (int i = blockIdx.x * blockDim.x + threadIdx.x; i < 2 * n; i += gridDim.x * blockDim.x) {
        if (i < n) h0f0[i] = 0.f; else h1f0[i - n] = 0.f;
    }
}

__global__ void clear_b(__half* __restrict__ h0a0, __half* __restrict__ h1a0,
                        __half* __restrict__ xd)
{
    const int n = HSN;
    const int t2 = 2 * n + BATCH * KC;
    for (int i = blockIdx.x * blockDim.x + threadIdx.x; i < t2; i += gridDim.x * blockDim.x) {
        if (i < n) h0a0[i] = __half(0.f);
        else if (i < 2 * n) h1a0[i - n] = __half(0.f);
        else xd[i - 2 * n] = __half(0.f);
    }
}

// ---------------- host ----------------
extern "C" void kernel_launch(void* const* d_in, const int* in_sizes, int n_in,
                              void* d_out, int out_size)
{
    const float* in_data  = (const float*)d_in[0];
    const float* last_loc = (const float*)d_in[1];
    const float* eWih0 = (const float*)d_in[3];
    const float* eWhh0 = (const float*)d_in[4];
    const float* ebih0 = (const float*)d_in[5];
    const float* ebhh0 = (const float*)d_in[6];
    const float* eWih1 = (const float*)d_in[7];
    const float* eWhh1 = (const float*)d_in[8];
    const float* ebih1 = (const float*)d_in[9];
    const float* ebhh1 = (const float*)d_in[10];
    const float* dWih0 = (const float*)d_in[11];
    const float* dWhh0 = (const float*)d_in[12];
    const float* dbih0 = (const float*)d_in[13];
    const float* dbhh0 = (const float*)d_in[14];
    const float* dWih1 = (const float*)d_in[15];
    const float* dWhh1 = (const float*)d_in[16];
    const float* dbih1 = (const float*)d_in[17];
    const float* dbhh1 = (const float*)d_in[18];
    const float* linW  = (const float*)d_in[19];
    const float* linb  = (const float*)d_in[20];

    float* outputs = (float*)d_out;
    float* hidden  = (float*)d_out + (size_t)BATCH * T_PRED * OUT_DIM;

    __half (*Wb)[WBIG];         cudaGetSymbolAddress((void**)&Wb, g_W);
    __half (*Wsm)[WSM];         cudaGetSymbolAddress((void**)&Wsm, g_Wsm);
    float (*h0f)[BATCH * H];    cudaGetSymbolAddress((void**)&h0f, g_h0f);
    float (*h1f)[BATCH * H];    cudaGetSymbolAddress((void**)&h1f, g_h1f);
    __half (*h0a)[HSN];         cudaGetSymbolAddress((void**)&h0a, g_h0a);
    __half (*h1a)[HSN];         cudaGetSymbolAddress((void**)&h1a, g_h1a);
    __half* xin = nullptr;      cudaGetSymbolAddress((void**)&xin, g_xin);
    __half* xll = nullptr;      cudaGetSymbolAddress((void**)&xll, g_ll);
    __half* xd  = nullptr;      cudaGetSymbolAddress((void**)&xd, g_xd);

    cudaFuncSetAttribute(gru_step_h, cudaFuncAttributeMaxDynamicSharedMemorySize, SMEM_BYTES);

    WPrep wp;
    wp.src[0] = eWhh0; wp.src[1] = eWih1; wp.src[2] = eWhh1;
    wp.src[3] = dWhh0; wp.src[4] = dWih1; wp.src[5] = dWhh1;
    wp.src[6] = eWih0; wp.src[7] = dWih0;
    prep_weights<<<dim3(512, 8), 256>>>(wp, Wb[0], Wsm[0]);
    prep_acts<<<1024, 256>>>(in_data, last_loc, xin, xll);
    clear_a<<<512, 256>>>(h0f[0], h1f[0]);
    clear_b<<<512, 256>>>(h0a[0], h1a[0], xd);

    dim3 grid(BATCH / MTILE, H / 32);   // (4, 30)
    int p0 = 0, p1 = 0;
    const int out_ld = T_PRED * OUT_DIM;
    const int hid_ld = T_PRED * 2 * H;

    // ---- encoder ----
    for (int t = 0; t < T_IN; ++t) {
        gru_step_h<<<grid, NTHR, SMEM_BYTES>>>(
            xin + (size_t)t * BATCH * KC, 1, 2,
            h0a[p0], Wsm[0], Wb[0],
            ebih0, ebhh0, h0f[p0], h0f[1 - p0], h0a[1 - p0],
            nullptr, 0);
        p0 ^= 1;
        gru_step_h<<<grid, NTHR, SMEM_BYTES>>>(
            h0a[p0], NCH, 10,
            h1a[p1], Wb[1], Wb[2],
            ebih1, ebhh1, h1f[p1], h1f[1 - p1], h1a[1 - p1],
            nullptr, 0);
        p1 ^= 1;
    }

    // ---- decoder ----
    for (int t = 0; t < T_PRED; ++t) {
        const __half* xAp = (t == 0) ? xll : xd;
        gru_step_h<<<grid, NTHR, SMEM_BYTES>>>(
            xAp, 1, 2,
            h0a[p0], Wsm[1], Wb[3],
            dbih0, dbhh0, h0f[p0], h0f[1 - p0], h0a[1 - p0],
            hidden + (size_t)t * 2 * H, hid_ld);
        p0 ^= 1;
        gru_step_h<<<grid, NTHR, SMEM_BYTES>>>(
            h0a[p0], NCH, 10,
            h1a[p1], Wb[4], Wb[5],
            dbih1, dbhh1, h1f[p1], h1f[1 - p1], h1a[1 - p1],
            hidden + (size_t)t * 2 * H + H, hid_ld);
        p1 ^= 1;
        linear_kernel<<<BATCH / 8, 256>>>(h1f[p1], linW, linb,
                                          outputs + (size_t)t * OUT_DIM, out_ld, xd);
    }
}

// round 16
// speedup vs baseline: 1.5915x; 1.0102x over previous
#include <cuda_runtime.h>
#include <cuda_fp16.h>
#include <math.h>
#include <stdint.h>

// ---------------- problem constants ----------------
#define BATCH 512
#define T_IN 64
#define IN_DIM 16
#define HS 32
#define OUT_DIM 32
#define H 960
#define G3 2880
#define T_PRED 48

#define KC 160              // K-chunk (divides 960)
#define NCH 6               // h-pass chunks
#define MTILE 128
#define NTILE 96            // 3 gates x 32 units
#define NTHR 256

// smem: [bias 1024B][2 stages]; fp16 rows: 160 elems (320B) + 16B pad = 336B
#define ROWB 336
#define ABYTES (MTILE * ROWB)      // 43008
#define BBYTES (NTILE * ROWB)      // 32256
#define STAGE (ABYTES + BBYTES)    // 75264
#define SMEM_BYTES (1024 + 2 * STAGE)   // 151552
// epilogue planes (alias stage ring after final sync)
#define MSTRIDE 100
#define N2STRIDE 36
#define N2OFF 51200

// ---------------- device scratch ----------------
#define WBIG (G3 * NCH * KC)
#define WSM  (G3 * KC)
#define HSN  (NCH * BATCH * KC)

__device__ __half g_W[6][WBIG];      // eWhh0,eWih1,eWhh1,dWhh0,dWih1,dWhh1
__device__ __half g_Wsm[2][WSM];     // eWih0, dWih0 (K padded to KC)
__device__ float  g_h0f[2][BATCH * H];
__device__ float  g_h1f[2][BATCH * H];
__device__ __half g_h0a[2][HSN];
__device__ __half g_h1a[2][HSN];
__device__ __half g_xin[T_IN * BATCH * KC];
__device__ __half g_ll[BATCH * KC];
__device__ __half g_xd[BATCH * KC];

// ---------------- helpers ----------------
__device__ __forceinline__ uint32_t smem_u32(const void* p) {
    uint32_t a;
    asm("{ .reg .u64 t; cvta.to.shared.u64 t, %1; cvt.u32.u64 %0, t; }" : "=r"(a) : "l"(p));
    return a;
}
__device__ __forceinline__ void cp16(uint32_t dst, const void* src) {
    asm volatile("cp.async.cg.shared.global [%0], [%1], 16;" :: "r"(dst), "l"(src) : "memory");
}
#define CP_COMMIT() asm volatile("cp.async.commit_group;" ::: "memory")
#define CP_WAIT0()  asm volatile("cp.async.wait_group 0;" ::: "memory")

__device__ __forceinline__ void ldm4(uint32_t (&r)[4], uint32_t a) {
    asm volatile("ldmatrix.sync.aligned.m8n8.x4.shared.b16 {%0,%1,%2,%3}, [%4];"
        : "=r"(r[0]), "=r"(r[1]), "=r"(r[2]), "=r"(r[3]) : "r"(a));
}
__device__ __forceinline__ void mma_f16(float (&d)[4], const uint32_t (&a)[4],
                                        uint32_t b0, uint32_t b1) {
    asm volatile(
        "mma.sync.aligned.m16n8k16.row.col.f32.f16.f16.f32 "
        "{%0,%1,%2,%3}, {%4,%5,%6,%7}, {%8,%9}, {%0,%1,%2,%3};"
        : "+f"(d[0]), "+f"(d[1]), "+f"(d[2]), "+f"(d[3])
        : "r"(a[0]), "r"(a[1]), "r"(a[2]), "r"(a[3]), "r"(b0), "r"(b1));
}
// fast transcendentals (args are O(10); far from overflow)
__device__ __forceinline__ float sigf(float v) {
    return __fdividef(1.0f, 1.0f + __expf(-v));
}
__device__ __forceinline__ float tanhfast(float x) {
    float t = __expf(2.0f * x);
    return 1.0f - __fdividef(2.0f, t + 1.0f);
}

// ---------------- fused GRU step (fp16 mma, K=160 chunks, 2-stage) ----------------
// xkk: kk-iterations for x-chunks (2 when x-K<=32, 10 when full)
__global__ __launch_bounds__(NTHR, 1)
void gru_step_h(const __half* __restrict__ xA, int ncx, int xkk,
                const __half* __restrict__ hA,
                const __half* __restrict__ w1, const __half* __restrict__ w2,
                const float* __restrict__ bih, const float* __restrict__ bhh,
                const float* __restrict__ hprevf, float* __restrict__ houtf,
                __half* __restrict__ hAout,
                float* __restrict__ hcat, int hcat_ld)
{
    extern __shared__ char smem[];
    float* sbias = (float*)smem;
    const uint32_t sb = smem_u32(smem);

    const int tid  = threadIdx.x;
    const int lane = tid & 31;
    const int w    = tid >> 5;
    const int wm   = w & 3;      // m-block (32 rows)
    const int wn   = w >> 2;     // n-half (48 cols)
    const int m0   = blockIdx.x * MTILE;
    const int ub   = blockIdx.y;
    const int nc   = ncx + NCH;

    if (tid < 192) {
        int g = (tid < 96) ? (tid >> 5) : ((tid - 96) >> 5);
        int j = tid & 31;
        sbias[tid] = (tid < 96) ? bih[g * H + ub * 32 + j] : bhh[g * H + ub * 32 + j];
    }

    // acc = r/z (both passes) + n-gate x-pass; accn = n-gate h-pass (wn==1 only)
    float acc[2][6][4];
    float accn[2][4][4];
#pragma unroll
    for (int m2 = 0; m2 < 2; ++m2) {
#pragma unroll
        for (int f = 0; f < 6; ++f)
#pragma unroll
            for (int i = 0; i < 4; ++i) acc[m2][f][i] = 0.f;
#pragma unroll
        for (int f = 0; f < 4; ++f)
#pragma unroll
            for (int i = 0; i < 4; ++i) accn[m2][f][i] = 0.f;
    }

    const int lrow = (lane & 7) + ((lane >> 3) & 1) * 8;
    const int lcol = (lane >> 4) * 16;
    const uint32_t aoff = (uint32_t)(wm * 32 + lrow) * ROWB + lcol;
    const uint32_t boff = ABYTES + (uint32_t)(wn * 48 + lrow) * ROWB + lcol;

    auto issue_load = [&](int c) {
        const __half* ap = (c < ncx) ? (xA + ((size_t)c * BATCH + m0) * KC)
                                     : (hA + ((size_t)(c - ncx) * BATCH + m0) * KC);
        const __half* bp = (c < ncx) ? (w1 + ((size_t)c * G3 + ub * NTILE) * KC)
                                     : (w2 + ((size_t)(c - ncx) * G3 + ub * NTILE) * KC);
        const char* asrc = (const char*)ap;
        const char* bsrc = (const char*)bp;
        uint32_t d = sb + 1024 + (uint32_t)(c & 1) * STAGE;
        if (xkk == 2 && c < ncx) {
            // trimmed x-chunk: only first 64B of each row carries data
            {   // A: 128 rows x 4 units = 512
                int u = tid;
                if (u < 512)
                    cp16(d + (u >> 2) * ROWB + (u & 3) * 16, asrc + (size_t)((u >> 2) * 20 + (u & 3)) * 16);
            }
            {   // B: 96 rows x 4 units = 384
                int u = tid - (NTHR - 0);   // second half? use same tid range guarded
                u = tid;
                if (u < 384)
                    cp16(d + ABYTES + (u >> 2) * ROWB + (u & 3) * 16, bsrc + (size_t)((u >> 2) * 20 + (u & 3)) * 16);
            }
            {   // remaining A units 256..511 handled above only if NTHR>=512; NTHR=256 so loop
                int u = tid + NTHR;
                if (u < 512)
                    cp16(d + (u >> 2) * ROWB + (u & 3) * 16, asrc + (size_t)((u >> 2) * 20 + (u & 3)) * 16);
                int ub2 = tid + NTHR;
                if (ub2 < 384)
                    cp16(d + ABYTES + (ub2 >> 2) * ROWB + (ub2 & 3) * 16, bsrc + (size_t)((ub2 >> 2) * 20 + (ub2 & 3)) * 16);
            }
        } else {
#pragma unroll
            for (int i = 0; i < 10; ++i) {             // A: 2560 x 16B
                int u = tid + i * NTHR;
                cp16(d + (u / 20) * ROWB + (u % 20) * 16, asrc + (size_t)u * 16);
            }
#pragma unroll
            for (int i = 0; i < 8; ++i) {              // B: 1920 x 16B
                int u = tid + i * NTHR;
                if (u < 1920)
                    cp16(d + ABYTES + (u / 20) * ROWB + (u % 20) * 16, bsrc + (size_t)u * 16);
            }
        }
        CP_COMMIT();
    };

    issue_load(0);

#define CHUNK_BODY(SPLIT, KKN)                                                  \
    {                                                                           \
        _Pragma("unroll")                                                       \
        for (int kk = 0; kk < KKN; ++kk) {                                      \
            uint32_t a0[4], a1[4], b0[4], b1[4], b2[4];                         \
            ldm4(a0, stage + aoff + kk * 32);                                   \
            ldm4(a1, stage + aoff + 16 * ROWB + kk * 32);                       \
            ldm4(b0, stage + boff + kk * 32);                                   \
            ldm4(b1, stage + boff + 16 * ROWB + kk * 32);                       \
            ldm4(b2, stage + boff + 32 * ROWB + kk * 32);                       \
            mma_f16(acc[0][0], a0, b0[0], b0[2]);                               \
            mma_f16(acc[1][0], a1, b0[0], b0[2]);                               \
            mma_f16(acc[0][1], a0, b0[1], b0[3]);                               \
            mma_f16(acc[1][1], a1, b0[1], b0[3]);                               \
            if (SPLIT) {                                                        \
                mma_f16(accn[0][0], a0, b1[0], b1[2]);                          \
                mma_f16(accn[1][0], a1, b1[0], b1[2]);                          \
                mma_f16(accn[0][1], a0, b1[1], b1[3]);                          \
                mma_f16(accn[1][1], a1, b1[1], b1[3]);                          \
                mma_f16(accn[0][2], a0, b2[0], b2[2]);                          \
                mma_f16(accn[1][2], a1, b2[0], b2[2]);                          \
                mma_f16(accn[0][3], a0, b2[1], b2[3]);                          \
                mma_f16(accn[1][3], a1, b2[1], b2[3]);                          \
            } else {                                                            \
                mma_f16(acc[0][2], a0, b1[0], b1[2]);                           \
                mma_f16(acc[1][2], a1, b1[0], b1[2]);                           \
                mma_f16(acc[0][3], a0, b1[1], b1[3]);                           \
                mma_f16(acc[1][3], a1, b1[1], b1[3]);                           \
                mma_f16(acc[0][4], a0, b2[0], b2[2]);                           \
                mma_f16(acc[1][4], a1, b2[0], b2[2]);                           \
                mma_f16(acc[0][5], a0, b2[1], b2[3]);                           \
                mma_f16(acc[1][5], a1, b2[1], b2[3]);                           \
            }                                                                   \
        }                                                                       \
    }

    // 2-stage double buffer: wait(0) -> barrier -> issue(c+1) -> consume(c)
    for (int c = 0; c < nc; ++c) {
        CP_WAIT0();
        __syncthreads();
        if (c + 1 < nc) issue_load(c + 1);
        const uint32_t stage = sb + 1024 + (uint32_t)(c & 1) * STAGE;
        if (c < ncx) {
            if (xkk == 2) CHUNK_BODY(0, 2) else CHUNK_BODY(0, 10)
        } else if (wn == 1) {
            CHUNK_BODY(1, 10)
        } else {
            CHUNK_BODY(0, 10)
        }
    }
#undef CHUNK_BODY
    __syncthreads();   // ring fully consumed before plane overwrite

    // ---------------- epilogue: accums -> smem planes -> gate math ----------------
    float* Mp = (float*)(smem + 1024);
    float* Np = (float*)(smem + 1024 + N2OFF);
    {
        const int rb = wm * 32 + (lane >> 2);
        const int cb = wn * 48 + (lane & 3) * 2;
#pragma unroll
        for (int m2 = 0; m2 < 2; ++m2) {
#pragma unroll
            for (int f = 0; f < 6; ++f) {
                int r = rb + m2 * 16;
                int cc = cb + f * 8;
                *(float2*)&Mp[r * MSTRIDE + cc]       = make_float2(acc[m2][f][0], acc[m2][f][1]);
                *(float2*)&Mp[(r + 8) * MSTRIDE + cc] = make_float2(acc[m2][f][2], acc[m2][f][3]);
            }
        }
        if (wn == 1) {
            const int cb2 = (lane & 3) * 2;
#pragma unroll
            for (int m2 = 0; m2 < 2; ++m2) {
#pragma unroll
                for (int f = 0; f < 4; ++f) {
                    int r = rb + m2 * 16;
                    int cc = cb2 + f * 8;
                    *(float2*)&Np[r * N2STRIDE + cc]       = make_float2(accn[m2][f][0], accn[m2][f][1]);
                    *(float2*)&Np[(r + 8) * N2STRIDE + cc] = make_float2(accn[m2][f][2], accn[m2][f][3]);
                }
            }
        }
    }
    __syncthreads();

    {
        const int row = tid >> 1;
        const int j0  = (tid & 1) * 16;
        const int brow = m0 + row;
        const int cj = ub / 5;
        const int kb = (ub % 5) * 32;

        float hv[16];
#pragma unroll
        for (int v = 0; v < 8; ++v) {
            int j = j0 + v * 2;
            float2 R  = *(float2*)&Mp[row * MSTRIDE + j];
            float2 Z  = *(float2*)&Mp[row * MSTRIDE + 32 + j];
            float2 NX = *(float2*)&Mp[row * MSTRIDE + 64 + j];
            float2 NH = *(float2*)&Np[row * N2STRIDE + j];
            float2 HP = *(const float2*)(hprevf + (size_t)brow * H + ub * 32 + j);
#pragma unroll
            for (int e = 0; e < 2; ++e) {
                int jj = j + e;
                float rr = sigf(((e ? R.y : R.x))  + sbias[jj]      + sbias[96 + jj]);
                float zz = sigf(((e ? Z.y : Z.x))  + sbias[32 + jj] + sbias[128 + jj]);
                float nn = tanhfast(((e ? NX.y : NX.x)) + sbias[64 + jj]
                                    + rr * (((e ? NH.y : NH.x)) + sbias[160 + jj]));
                hv[j - j0 + e] = (1.0f - zz) * nn + zz * (e ? HP.y : HP.x);
            }
        }
        const size_t ob = (size_t)brow * H + ub * 32 + j0;
#pragma unroll
        for (int q = 0; q < 4; ++q)
            *(float4*)(houtf + ob + q * 4) = make_float4(hv[q*4], hv[q*4+1], hv[q*4+2], hv[q*4+3]);
        if (hcat) {
            const size_t cbo = (size_t)brow * hcat_ld + ub * 32 + j0;
#pragma unroll
            for (int q = 0; q < 4; ++q)
                *(float4*)(hcat + cbo + q * 4) = make_float4(hv[q*4], hv[q*4+1], hv[q*4+2], hv[q*4+3]);
        }
        __half hh[16];
#pragma unroll
        for (int i = 0; i < 16; ++i) hh[i] = __float2half_rn(hv[i]);
        const size_t so = ((size_t)cj * BATCH + brow) * KC + kb + j0;
        *(uint4*)(hAout + so)     = ((uint4*)hh)[0];
        *(uint4*)(hAout + so + 8) = ((uint4*)hh)[1];
    }
}

// ---------------- linear head ----------------
__global__ __launch_bounds__(256)
void linear_kernel(const float* __restrict__ h,
                   const float* __restrict__ W, const float* __restrict__ bias,
                   float* __restrict__ out, int out_ld,
                   __half* __restrict__ xdA)
{
    __shared__ float Ws[64][33];
    __shared__ float hs[8][64];
    const int tid = threadIdx.x;
    const int o = tid & 31;
    const int bl = tid >> 5;
    const int b0 = blockIdx.x * 8;

    float acc = 0.f;
    for (int k0 = 0; k0 < H; k0 += 64) {
#pragma unroll
        for (int i = 0; i < 8; ++i) {
            int idx = tid + i * 256;
            Ws[idx & 63][idx >> 6] = W[(size_t)(idx >> 6) * H + k0 + (idx & 63)];
        }
#pragma unroll
        for (int i = 0; i < 2; ++i) {
            int idx = tid + i * 256;
            hs[idx >> 6][idx & 63] = h[(size_t)(b0 + (idx >> 6)) * H + k0 + (idx & 63)];
        }
        __syncthreads();
#pragma unroll
        for (int kk = 0; kk < 64; ++kk)
            acc = fmaf(hs[bl][kk], Ws[kk][o], acc);
        __syncthreads();
    }
    float v = acc + bias[o];
    int b = b0 + bl;
    out[(size_t)b * out_ld + o] = v;
    xdA[(size_t)b * KC + o] = __float2half_rn(v);
}

// ---------------- prep (2 launches + 1 clear) ----------------
struct WPrep { const float* src[8]; };

__global__ void prep_all(WPrep wp, __half* __restrict__ Wb, __half* __restrict__ Wsm,
                         const float* __restrict__ in_data, const float* __restrict__ ll_src,
                         __half* __restrict__ xin, __half* __restrict__ xll)
{
    const int y = blockIdx.y;
    if (y < 6) {
        const float* W = wp.src[y];
        __half* dst = Wb + (size_t)y * WBIG;
        int total = G3 * NCH * KC;
        for (int idx = blockIdx.x * blockDim.x + threadIdx.x; idx < total; idx += gridDim.x * blockDim.x) {
            int k = idx % KC;
            int q = idx / KC;
            int n = q % G3;
            int c = q / G3;
            int ubl = n / 96, rem = n % 96, g = rem >> 5, jj = rem & 31;
            int row = g * H + ubl * 32 + jj;
            dst[idx] = __float2half_rn(W[(size_t)row * H + c * KC + k]);
        }
    } else if (y < 8) {
        const float* W = wp.src[y];
        const int K = (y == 6) ? IN_DIM : HS;
        __half* dst = Wsm + (size_t)(y - 6) * WSM;
        int total = G3 * KC;
        for (int idx = blockIdx.x * blockDim.x + threadIdx.x; idx < total; idx += gridDim.x * blockDim.x) {
            int k = idx % KC;
            int n = idx / KC;
            int ubl = n / 96, rem = n % 96, g = rem >> 5, jj = rem & 31;
            int row = g * H + ubl * 32 + jj;
            float v = (k < K) ? W[(size_t)row * K + k] : 0.f;
            dst[idx] = __float2half_rn(v);
        }
    } else {
        const int t1 = T_IN * BATCH * KC;
        const int t2 = t1 + BATCH * KC;
        for (int idx = blockIdx.x * blockDim.x + threadIdx.x; idx < t2; idx += gridDim.x * blockDim.x) {
            if (idx < t1) {
                int k = idx % KC;
                int q = idx / KC;
                int b = q & (BATCH - 1);
                int t = q >> 9;
                float v = (k < IN_DIM) ? in_data[((size_t)b * T_IN + t) * IN_DIM + k] : 0.f;
                xin[idx] = __float2half_rn(v);
            } else {
                int i = idx - t1;
                int k = i % KC;
                int b = i / KC;
                float v = (k < HS) ? ll_src[(size_t)b * HS + k] : 0.f;
                xll[i] = __float2half_rn(v);
            }
        }
    }
}

__global__ void clear_all(float* __restrict__ h0f0, float* __restrict__ h1f0,
                          __half* __restrict__ h0a0, __half* __restrict__ h1a0,
                          __half* __restrict__ xd)
{
    const int nf = BATCH * H;
    const int nh = HSN;
    const int t1 = 2 * nf;
    const int t2 = t1 + 2 * nh;
    const int t3 = t2 + BATCH * KC;
    for (int i = blockIdx.x * blockDim.x + threadIdx.x; i < t3; i += gridDim.x * blockDim.x) {
        if (i < nf) h0f0[i] = 0.f;
        else if (i < t1) h1f0[i - nf] = 0.f;
        else if (i < t1 + nh) h0a0[i - t1] = __half(0.f);
        else if (i < t2) h1a0[i - t1 - nh] = __half(0.f);
        else xd[i - t2] = __half(0.f);
    }
}

// ---------------- host ----------------
extern "C" void kernel_launch(void* const* d_in, const int* in_sizes, int n_in,
                              void* d_out, int out_size)
{
    const float* in_data  = (const float*)d_in[0];
    const float* last_loc = (const float*)d_in[1];
    const float* eWih0 = (const float*)d_in[3];
    const float* eWhh0 = (const float*)d_in[4];
    const float* ebih0 = (const float*)d_in[5];
    const float* ebhh0 = (const float*)d_in[6];
    const float* eWih1 = (const float*)d_in[7];
    const float* eWhh1 = (const float*)d_in[8];
    const float* ebih1 = (const float*)d_in[9];
    const float* ebhh1 = (const float*)d_in[10];
    const float* dWih0 = (const float*)d_in[11];
    const float* dWhh0 = (const float*)d_in[12];
    const float* dbih0 = (const float*)d_in[13];
    const float* dbhh0 = (const float*)d_in[14];
    const float* dWih1 = (const float*)d_in[15];
    const float* dWhh1 = (const float*)d_in[16];
    const float* dbih1 = (const float*)d_in[17];
    const float* dbhh1 = (const float*)d_in[18];
    const float* linW  = (const float*)d_in[19];
    const float* linb  = (const float*)d_in[20];

    float* outputs = (float*)d_out;
    float* hidden  = (float*)d_out + (size_t)BATCH * T_PRED * OUT_DIM;

    __half (*Wb)[WBIG];         cudaGetSymbolAddress((void**)&Wb, g_W);
    __half (*Wsm)[WSM];         cudaGetSymbolAddress((void**)&Wsm, g_Wsm);
    float (*h0f)[BATCH * H];    cudaGetSymbolAddress((void**)&h0f, g_h0f);
    float (*h1f)[BATCH * H];    cudaGetSymbolAddress((void**)&h1f, g_h1f);
    __half (*h0a)[HSN];         cudaGetSymbolAddress((void**)&h0a, g_h0a);
    __half (*h1a)[HSN];         cudaGetSymbolAddress((void**)&h1a, g_h1a);
    __half* xin = nullptr;      cudaGetSymbolAddress((void**)&xin, g_xin);
    __half* xll = nullptr;      cudaGetSymbolAddress((void**)&xll, g_ll);
    __half* xd  = nullptr;      cudaGetSymbolAddress((void**)&xd, g_xd);

    cudaFuncSetAttribute(gru_step_h, cudaFuncAttributeMaxDynamicSharedMemorySize, SMEM_BYTES);

    WPrep wp;
    wp.src[0] = eWhh0; wp.src[1] = eWih1; wp.src[2] = eWhh1;
    wp.src[3] = dWhh0; wp.src[4] = dWih1; wp.src[5] = dWhh1;
    wp.src[6] = eWih0; wp.src[7] = dWih0;
    prep_all<<<dim3(512, 9), 256>>>(wp, Wb[0], Wsm[0], in_data, last_loc, xin, xll);
    clear_all<<<512, 256>>>(h0f[0], h1f[0], h0a[0], h1a[0], xd);

    dim3 grid(BATCH / MTILE, H / 32);   // (4, 30)
    int p0 = 0, p1 = 0;
    const int out_ld = T_PRED * OUT_DIM;
    const int hid_ld = T_PRED * 2 * H;

    // ---- encoder ----
    for (int t = 0; t < T_IN; ++t) {
        gru_step_h<<<grid, NTHR, SMEM_BYTES>>>(
            xin + (size_t)t * BATCH * KC, 1, 2,
            h0a[p0], Wsm[0], Wb[0],
            ebih0, ebhh0, h0f[p0], h0f[1 - p0], h0a[1 - p0],
            nullptr, 0);
        p0 ^= 1;
        gru_step_h<<<grid, NTHR, SMEM_BYTES>>>(
            h0a[p0], NCH, 10,
            h1a[p1], Wb[1], Wb[2],
            ebih1, ebhh1, h1f[p1], h1f[1 - p1], h1a[1 - p1],
            nullptr, 0);
        p1 ^= 1;
    }

    // ---- decoder ----
    for (int t = 0; t < T_PRED; ++t) {
        const __half* xAp = (t == 0) ? xll : xd;
        gru_step_h<<<grid, NTHR, SMEM_BYTES>>>(
            xAp, 1, 2,
            h0a[p0], Wsm[1], Wb[3],
            dbih0, dbhh0, h0f[p0], h0f[1 - p0], h0a[1 - p0],
            hidden + (size_t)t * 2 * H, hid_ld);
        p0 ^= 1;
        gru_step_h<<<grid, NTHR, SMEM_BYTES>>>(
            h0a[p0], NCH, 10,
            h1a[p1], Wb[4], Wb[5],
            dbih1, dbhh1, h1f[p1], h1f[1 - p1], h1a[1 - p1],
            hidden + (size_t)t * 2 * H + H, hid_ld);
        p1 ^= 1;
        linear_kernel<<<BATCH / 8, 256>>>(h1f[p1], linW, linb,
                                          outputs + (size_t)t * OUT_DIM, out_ld, xd);
    }
}